// round 3
// baseline (speedup 1.0000x reference)
#include <cuda_runtime.h>
#include <math.h>

#define NH 2
#define NB 2048
#define NM 64
#define ND 16
#define NREL 32

// Q[b][r][j] = sum_i R[r][i][j] * item_e[b][i]   -> [2048][32][16] floats = 4MB
__device__ float4 Q_buf[NB * NREL * ND / 4];

// ---------------- Kernel 1: per-item relation projections ----------------
// 256 blocks x 128 threads; each block handles 8 consecutive b.
// thread t: r = t>>2 (0..31), jg = t&3 (float4 column group).
__global__ __launch_bounds__(128, 8)
void qprep_kernel(const int* __restrict__ items,
                  const float* __restrict__ ent,
                  const float* __restrict__ relm)
{
    const int b0 = blockIdx.x * 8;
    const int t  = threadIdx.x;
    const int r  = t >> 2;
    const int jg = t & 3;

    __shared__ __align__(16) float item_s[8][ND];

    // load 8 item embeddings (8*16 = 128 floats, one per thread)
    {
        const int bb = t >> 4;
        const int d  = t & 15;
        item_s[bb][d] = ent[(size_t)items[b0 + bb] * ND + d];
    }
    __syncthreads();

    const float4* relm4 = (const float4*)relm;

    float4 acc[8];
    #pragma unroll
    for (int bb = 0; bb < 8; bb++) acc[bb] = make_float4(0.f, 0.f, 0.f, 0.f);

    #pragma unroll
    for (int i = 0; i < ND; i++) {
        float4 Rv = relm4[r * 64 + i * 4 + jg];   // R[r][i][jg*4 .. +3]
        #pragma unroll
        for (int bb = 0; bb < 8; bb++) {
            float s = item_s[bb][i];
            acc[bb].x += s * Rv.x;
            acc[bb].y += s * Rv.y;
            acc[bb].z += s * Rv.z;
            acc[bb].w += s * Rv.w;
        }
    }

    #pragma unroll
    for (int bb = 0; bb < 8; bb++) {
        // float4 index: (b)*128 + r*4 + jg ; r*4+jg == t  -> fully coalesced
        Q_buf[(size_t)(b0 + bb) * 128 + t] = acc[bb];
    }
}

// ---------------- Kernel 2: gathers + softmax + output ----------------
// 2048 blocks x 128 threads. Quad (4 threads) per slot; 32 slots/pass, 4 passes.
__global__ __launch_bounds__(128, 12)
void ripple_kernel(const int* __restrict__ items,
                   const int* __restrict__ heads,
                   const int* __restrict__ rels,
                   const int* __restrict__ tails,
                   const float* __restrict__ ent,
                   float* __restrict__ out)
{
    const int b    = blockIdx.x;
    const int t    = threadIdx.x;      // 0..127
    const int lane = t & 31;
    const int wid  = t >> 5;
    const int sub  = t & 3;            // position within quad
    const int quad = t >> 2;           // 0..31

    __shared__ __align__(16) float item_s[ND];
    __shared__ __align__(16) float4 q_s[NREL * 4];   // Q[b] staged: [r][jg]
    __shared__ float logit_s[NH * NM];
    __shared__ float td_s[NH * NM];
    __shared__ float red_s[8];

    // ---- stage item embedding + Q[b] (contiguous, coalesced) ----
    if (t < ND) item_s[t] = ent[(size_t)items[b] * ND + t];
    q_s[t] = Q_buf[(size_t)b * 128 + t];
    __syncthreads();

    const float4* ent4 = (const float4*)ent;
    const float4* ip   = (const float4*)item_s;
    const float4  iv   = ip[sub];

    // ---- gather passes: 4 threads per slot, each loads one float4 ----
    #pragma unroll
    for (int pass = 0; pass < 4; pass++) {
        const int s    = pass * 32 + quad;       // slot 0..127
        const int hop  = s >> 6;
        const int m    = s & 63;
        const int gidx = hop * (NB * NM) + b * NM + m;

        const int hidx = heads[gidx];
        const int ridx = rels[gidx];
        const int tidx = tails[gidx];

        float4 hv = ent4[(size_t)hidx * 4 + sub];
        float4 tv = ent4[(size_t)tidx * 4 + sub];
        float4 qv = q_s[ridx * 4 + sub];

        float pl = qv.x * hv.x + qv.y * hv.y + qv.z * hv.z + qv.w * hv.w;
        float pt = iv.x * tv.x + iv.y * tv.y + iv.z * tv.z + iv.w * tv.w;

        // reduce over the 4-lane quad
        pl += __shfl_xor_sync(0xffffffffu, pl, 1);
        pl += __shfl_xor_sync(0xffffffffu, pl, 2);
        pt += __shfl_xor_sync(0xffffffffu, pt, 1);
        pt += __shfl_xor_sync(0xffffffffu, pt, 2);

        logit_s[s] = pl;   // all 4 lanes write same value (benign)
        td_s[s]    = pt;
    }
    __syncthreads();

    // ---- softmax over 64 slots per hop; thread t owns slot t ----
    const int hop = t >> 6;
    float logit = logit_s[t];
    float td    = td_s[t];

    float mx = logit;
    #pragma unroll
    for (int o = 16; o > 0; o >>= 1)
        mx = fmaxf(mx, __shfl_xor_sync(0xffffffffu, mx, o));
    if (lane == 0) red_s[wid] = mx;
    __syncthreads();
    mx = fmaxf(red_s[hop * 2], red_s[hop * 2 + 1]);

    float e = __expf(logit - mx);
    float sm = e;
    #pragma unroll
    for (int o = 16; o > 0; o >>= 1)
        sm += __shfl_xor_sync(0xffffffffu, sm, o);
    if (lane == 0) red_s[4 + wid] = sm;
    __syncthreads();
    sm = red_s[4 + hop * 2] + red_s[4 + hop * 2 + 1];

    const float pi = e / sm;

    // ---- contribution: pi * (tail . item); block-reduce ----
    float c = pi * td;
    #pragma unroll
    for (int o = 16; o > 0; o >>= 1)
        c += __shfl_xor_sync(0xffffffffu, c, o);
    __syncthreads();                 // protect red_s[0..3] reuse
    if (lane == 0) red_s[wid] = c;
    __syncthreads();

    if (t == 0) {
        float total = red_s[0] + red_s[1] + red_s[2] + red_s[3];
        out[b] = 1.f / (1.f + __expf(-total));
    }
}

extern "C" void kernel_launch(void* const* d_in, const int* in_sizes, int n_in,
                              void* d_out, int out_size)
{
    const int*   items = (const int*)d_in[0];
    const int*   heads = (const int*)d_in[1];
    const int*   rels  = (const int*)d_in[2];
    const int*   tails = (const int*)d_in[3];
    const float* ent   = (const float*)d_in[4];
    const float* relm  = (const float*)d_in[5];
    float*       out   = (float*)d_out;

    qprep_kernel<<<NB / 8, 128>>>(items, ent, relm);
    ripple_kernel<<<NB, 128>>>(items, heads, rels, tails, ent, out);
}